// round 13
// baseline (speedup 1.0000x reference)
#include <cuda_runtime.h>
#include <math.h>

// Problem constants (fixed by setup_inputs)
#define B_  2
#define T_  8
#define M_  900
#define H_  27
#define W_  27
#define D_  1024
#define PATCH_ 14

#define NBLK   M_                          // 900 blocks; ALL resident in one wave @ occ7
#define NPAIR_DENOM (B_ * (T_ - 1) * M_)   // 12600, mean denominator
#define FP_SCALE 4194304.0f                // 2^22 fixed-point scale

// Single deterministic accumulator: bits [0:52) fixed-point sum, bits [52:64) block count.
__device__ unsigned long long g_sum = 0ull;   // reset by the last block each launch

// L1 over 4 dims: abs folds into FADD source modifiers
__device__ __forceinline__ float l1_4(const float4& a, const float4& b)
{
    float d0 = a.x - b.x, d1 = a.y - b.y, d2 = a.z - b.z, d3 = a.w - b.w;
    return (fabsf(d0) + fabsf(d1)) + (fabsf(d2) + fabsf(d3));
}

__global__ __launch_bounds__(256, 7)      // 36-reg budget -> 7 blocks/SM, 1036 slots >= 900
void gather_l1_smem_kernel(const float* __restrict__ features,
                           const float* __restrict__ tracks,
                           const int* __restrict__ vis,   // bool stored as int32
                           float* __restrict__ out)
{
    __shared__ unsigned s_off[2 * T_];    // dead-row-redirected row offsets (elements)
    __shared__ float    s_mc[2 * T_];     // consec pair masks, index bb*8+t (t=0..6)
    __shared__ float    s_mr[2 * T_];     // ref    pair masks, index bb*8+t (t=0..6)
    __shared__ float    s_warp[8];

    const int m    = blockIdx.x;          // 0..899
    const int tid  = threadIdx.x;
    const int lane = tid & 31;
    const int wid  = tid >> 5;

    // --- Warp 0 stages all per-track metadata into smem.
    if (wid == 0) {
        unsigned my_off = 0;
        int      my_vis = 0;
        if (lane < 2 * T_) {
            const int bb = lane >> 3;
            const int t  = lane & 7;
            const float2 tr = *(const float2*)(tracks
                + (unsigned)(((bb * T_ + t) * M_ + m) * 2));
            // nearest patch center c_j = 14j+7 -> j = clamp(floor(x/14), 0, 26)
            int j = (int)floorf(tr.x * (1.0f / PATCH_));
            int i = (int)floorf(tr.y * (1.0f / PATCH_));
            j = min(W_ - 1, max(0, j));
            i = min(H_ - 1, max(0, i));
            my_off = (unsigned)((bb * T_ + t) * (H_ * W_) + i * W_ + j) << 10;
            my_vis = vis[(unsigned)((bb * T_ + t) * M_ + m)];
        }
        const unsigned blt = __ballot_sync(0xffffffffu, my_vis != 0);
        if (lane < 2 * T_) {
            const int bb = lane >> 3;
            const int t  = lane & 7;
            const unsigned g = (blt >> (bb * 8)) & 0xFFu;   // vis bits of this batch
            const int self = (g >> t) & 1;
            // Row t contributes iff visible AND has a visible partner (t-1, t+1, or 0).
            int alive;
            if (t == 0)           alive = self & ((g & 0xFEu) ? 1 : 0);
            else if (t == T_ - 1) alive = self & (((g >> (T_ - 2)) & 1) | (g & 1));
            else                  alive = self & (((g >> (t - 1)) & 1)
                                                | ((g >> (t + 1)) & 1) | (g & 1));
            s_off[lane] = alive ? my_off : 0u;    // dead rows -> hot row 0 (L2-resident)
            if (t < T_ - 1) {
                const int nxt = (g >> (t + 1)) & 1;
                s_mc[lane] = (float)(self & nxt);         // mask for pair (t, t+1)
                s_mr[lane] = (float)((g & 1) & nxt);      // mask for pair (0, t+1)
            }
        }
    }
    __syncthreads();

    const unsigned tcol = (unsigned)tid << 2;   // this thread's float4 lane in a row
    float acc = 0.0f;

#pragma unroll
    for (int bb = 0; bb < B_; bb++) {
        const int sb = bb * T_;

        // --- Gather 8 rows; 8 independent LDG.128 per thread (full MLP).
        // Offsets read from smem at point of use -> no register arrays.
        float4 pf[T_];
#pragma unroll
        for (int t = 0; t < T_; t++)
            pf[t] = *(const float4*)(features + (s_off[sb + t] + tcol));

        // --- 13 distinct pairs; pair (0,1) serves both consec and ref terms.
        float l01 = l1_4(pf[0], pf[1]);
        float acc_c = s_mc[sb] * l01;
        float acc_r = s_mr[sb] * l01;
#pragma unroll
        for (int t = 1; t < T_ - 1; t++) {
            acc_c = fmaf(s_mc[sb + t], l1_4(pf[t], pf[t + 1]), acc_c);
            acc_r = fmaf(s_mr[sb + t], l1_4(pf[0], pf[t + 1]), acc_r);
        }
        acc += acc_c + acc_r;             // fixed order -> deterministic
    }

    // --- Block reduction: warp shuffle, then 8 warp sums via shared
#pragma unroll
    for (int o = 16; o > 0; o >>= 1)
        acc += __shfl_down_sync(0xffffffffu, acc, o);

    if (lane == 0) s_warp[wid] = acc;
    __syncthreads();

    // --- Deterministic fixed-point atomic epilogue (no fence, no spin, no re-read).
    if (tid == 0) {
        float s = 0.0f;
#pragma unroll
        for (int w = 0; w < 8; w++) s += s_warp[w];
        unsigned long long mine = (1ull << 52)
                                + (unsigned long long)llrintf(s * FP_SCALE);
        unsigned long long old = atomicAdd(&g_sum, mine);
        if ((old >> 52) == (unsigned long long)(NBLK - 1)) {
            unsigned long long total = (old + mine) & ((1ull << 52) - 1ull);
            out[0] = (float)(0.01 * (double)total
                             / ((double)FP_SCALE * (double)NPAIR_DENOM));
            g_sum = 0ull;                 // reset for next graph replay (all adds done)
        }
    }
}

extern "C" void kernel_launch(void* const* d_in, const int* in_sizes, int n_in,
                              void* d_out, int out_size)
{
    const float* features = (const float*)d_in[0];  // [B*T, H*W, D] f32
    const float* tracks   = (const float*)d_in[1];  // [B, T, M, 2]  f32
    const int*   vis      = (const int*)d_in[2];    // [B, T, M]     bool->int32
    float*       out      = (float*)d_out;

    gather_l1_smem_kernel<<<NBLK, 256>>>(features, tracks, vis, out);
}

// round 14
// speedup vs baseline: 1.0239x; 1.0239x over previous
#include <cuda_runtime.h>
#include <math.h>

// Problem constants (fixed by setup_inputs)
#define B_  2
#define T_  8
#define M_  900
#define H_  27
#define W_  27
#define D_  1024
#define PATCH_ 14

#define NBLK   M_                          // 900 blocks, one per track m (both batches)
#define NPAIR_DENOM (B_ * (T_ - 1) * M_)   // 12600, mean denominator
#define FP_SCALE 4194304.0f                // 2^22 fixed-point scale

// Single deterministic accumulator: bits [0:52) fixed-point sum, bits [52:64) block count.
__device__ unsigned long long g_sum = 0ull;   // reset by the last block each launch

// L1 over 4 dims: abs folds into FADD source modifiers
__device__ __forceinline__ float l1_4(const float4& a, const float4& b)
{
    float d0 = a.x - b.x, d1 = a.y - b.y, d2 = a.z - b.z, d3 = a.w - b.w;
    return (fabsf(d0) + fabsf(d1)) + (fabsf(d2) + fabsf(d3));
}

__global__ __launch_bounds__(256, 6)      // R12-proven: 42-reg budget, 6 blocks/SM
void gather_l1_atomic_kernel(const float* __restrict__ features,
                             const float* __restrict__ tracks,
                             const int* __restrict__ vis,   // bool stored as int32
                             float* __restrict__ out)
{
    const int m    = blockIdx.x;          // 0..899
    const int tid  = threadIdx.x;         // 256 threads = 1024 floats / 4
    const int lane = tid & 31;
    const int wid  = tid >> 5;

    // --- Lanes 0..15 of EVERY warp (no block barrier): lane<8 -> (b=0, t=lane),
    // lane>=8 -> (b=1, t=lane-8). Redundant across warps; L1 broadcast makes it cheap.
    unsigned my_off = 0;
    int      my_vis = 0;
    if (lane < 2 * T_) {
        const int bb = lane >> 3;
        const int t  = lane & 7;
        const float2 tr = *(const float2*)(tracks
            + (unsigned)(((bb * T_ + t) * M_ + m) * 2));
        // nearest patch center c_j = 14j+7 -> j = clamp(floor(x/14), 0, 26)
        int j = (int)floorf(tr.x * (1.0f / PATCH_));
        int i = (int)floorf(tr.y * (1.0f / PATCH_));
        j = min(W_ - 1, max(0, j));
        i = min(H_ - 1, max(0, i));
        my_off = (unsigned)((bb * T_ + t) * (H_ * W_) + i * W_ + j) << 10;
        my_vis = vis[(unsigned)((bb * T_ + t) * M_ + m)];
    }
    // One ballot gives both batches' visibility bitmasks to every thread.
    const unsigned blt = __ballot_sync(0xffffffffu, my_vis != 0);
    const unsigned tcol = (unsigned)tid << 2;

    float acc = 0.0f;

#pragma unroll
    for (int bb = 0; bb < B_; bb++) {
        const int sb = bb * T_;
        const unsigned g   = (blt >> (bb * 8)) & 0xFFu;   // vis bits, frames 0..7
        const unsigned adj = g & (g >> 1);                // bit t: pair (t, t+1) alive
        const unsigned ref = (g & 1u) ? (g >> 1) : 0u;    // bit t: pair (0, t+1) alive

        // Warp-uniform skip: no contributing pair in this batch (same for whole block).
        if ((adj | ref) == 0u) continue;

        // Alive rows: row t contributes iff vis[t] and it has a visible partner.
        unsigned alive = g & ((g << 1) | (g >> 1) | ((g & 1u) ? 0xFEu : 0u));
        if ((g & 1u) && (g & 0xFEu)) alive |= 1u;         // row 0 alive iff any partner

        // --- Gather 8 rows; 8 independent LDG.128 (full MLP). Dead rows redirect
        // to row 0 (grid-wide hot in L1/L2, ~no DRAM cost); their terms multiply by 0.
        float4 pf[T_];
#pragma unroll
        for (int t = 0; t < T_; t++) {
            unsigned off = __shfl_sync(0xffffffffu, my_off, sb + t);
            off = ((alive >> t) & 1u) ? off : 0u;
            pf[t] = *(const float4*)(features + (off + tcol));
        }

        // --- 13 distinct pairs; pair (0,1) serves both consec and ref terms.
        float l01 = l1_4(pf[0], pf[1]);
        float m01 = (float)(adj & 1u);                    // == ref&1 when g0 set
        float acc_c = m01 * l01;
        float acc_r = m01 * l01;
#pragma unroll
        for (int t = 1; t < T_ - 1; t++) {
            float mc = (float)((adj >> t) & 1u);
            float mr = (float)((ref >> t) & 1u);
            acc_c = fmaf(mc, l1_4(pf[t], pf[t + 1]), acc_c);
            acc_r = fmaf(mr, l1_4(pf[0], pf[t + 1]), acc_r);
        }
        acc += acc_c + acc_r;             // fixed order -> deterministic
    }

    // --- Block reduction: warp shuffle, then 8 warp sums via shared
#pragma unroll
    for (int o = 16; o > 0; o >>= 1)
        acc += __shfl_down_sync(0xffffffffu, acc, o);

    __shared__ float s_warp[8];
    if (lane == 0) s_warp[wid] = acc;
    __syncthreads();

    // --- Deterministic fixed-point atomic epilogue (no fence, no spin, no re-read):
    // integer adds commute exactly; count rides in bits [52:64) of the same word.
    if (tid == 0) {
        float s = 0.0f;
#pragma unroll
        for (int w = 0; w < 8; w++) s += s_warp[w];
        unsigned long long mine = (1ull << 52)
                                + (unsigned long long)llrintf(s * FP_SCALE);
        unsigned long long old = atomicAdd(&g_sum, mine);
        if ((old >> 52) == (unsigned long long)(NBLK - 1)) {
            unsigned long long total = (old + mine) & ((1ull << 52) - 1ull);
            out[0] = (float)(0.01 * (double)total
                             / ((double)FP_SCALE * (double)NPAIR_DENOM));
            g_sum = 0ull;                 // reset for next graph replay (all adds done)
        }
    }
}

extern "C" void kernel_launch(void* const* d_in, const int* in_sizes, int n_in,
                              void* d_out, int out_size)
{
    const float* features = (const float*)d_in[0];  // [B*T, H*W, D] f32
    const float* tracks   = (const float*)d_in[1];  // [B, T, M, 2]  f32
    const int*   vis      = (const int*)d_in[2];    // [B, T, M]     bool->int32
    float*       out      = (float*)d_out;

    gather_l1_atomic_kernel<<<NBLK, 256>>>(features, tracks, vis, out);
}